// round 4
// baseline (speedup 1.0000x reference)
#include <cuda_runtime.h>
#include <math.h>

#define NWIRES 9
#define NLAYERS 4
#define DDIM 512
#define BATCH 64
#define PPAR 72
#define NGATES 36
#define EMBED 512

// Scratch (allocation-free: __device__ globals)
__device__ float g_params[BATCH * PPAR];
__device__ float g_coef[BATCH * NGATES * 4];   // c, s, cphi, sphi per gate
__device__ float g_scal[BATCH * 4];            // a1, a2, cos th
__device__ float g_Uv[BATCH * DDIM];

// dynamic smem layout for k2
#define SM_GF    0          // 144 floats (576B)
#define SM_PH    640        // float2 ph[4][16][32] = 16384B
#define SM_EXCH  17152      // 16 warps x 1024 floats (double buffer) = 65536B
#define SM_TOTAL (17152 + 65536)

// ---------------------------------------------------------------------------
// K1: MLP -> params, gate trig coefficients, rank-2 scalars, zero Uv
// ---------------------------------------------------------------------------
__global__ __launch_bounds__(512) void k1_params(
        const float* __restrict__ t, const float* __restrict__ w1,
        const float* __restrict__ b1, const float* __restrict__ w2,
        const float* __restrict__ b2) {
    int b = blockIdx.x;
    int tid = threadIdx.x;
    int w = tid >> 5, lane = tid & 31;
    __shared__ float h[EMBED];
    __shared__ float p[PPAR];

    float tv = t[b];
    {
        float x = fmaf(tv, w1[tid], b1[tid]);
        h[tid] = x / (1.f + expf(-x));   // silu
    }
    if (tid < PPAR) p[tid] = 0.f;
    __syncthreads();

    float a0 = 0.f, a1v = 0.f, a2v = 0.f;
    const float* w2base = w2 + (w * 32) * PPAR;
#pragma unroll 8
    for (int k = 0; k < 32; k++) {
        float hv = h[w * 32 + k];
        const float* row = w2base + k * PPAR;
        a0  = fmaf(hv, row[lane], a0);
        a1v = fmaf(hv, row[lane + 32], a1v);
        if (lane < 8) a2v = fmaf(hv, row[lane + 64], a2v);
    }
    atomicAdd(&p[lane], a0);
    atomicAdd(&p[lane + 32], a1v);
    if (lane < 8) atomicAdd(&p[lane + 64], a2v);
    __syncthreads();

    if (tid < PPAR) {
        float v = p[tid] + b2[tid];
        p[tid] = v;
        g_params[b * PPAR + tid] = v;
    }
    g_Uv[b * DDIM + tid] = 0.f;
    __syncthreads();

    if (tid < NGATES) {
        float thy = p[2 * tid], thz = p[2 * tid + 1];
        float* dst = &g_coef[(b * NGATES + tid) * 4];
        dst[0] = cosf(0.5f * thy);
        dst[1] = sinf(0.5f * thy);
        dst[2] = cosf(0.5f * thz);
        dst[3] = sinf(0.5f * thz);
    }
    if (tid == 0) {
        float s2 = 0.f;
        for (int j = 1; j < PPAR; j++) { float vj = 0.01f * p[j]; s2 = fmaf(vj, vj, s2); }
        float th = sqrtf(s2);
        float ct = cosf(th);
        float a1, a2;
        if (th > 1e-6f) { a1 = sinf(th) / th; a2 = (1.f - ct) / s2; }
        else            { a1 = 1.f - s2 * (1.f / 6.f); a2 = 0.5f; }
        g_scal[b * 4 + 0] = a1;
        g_scal[b * 4 + 1] = a2;
        g_scal[b * 4 + 2] = ct;
    }
}

// ---------------------------------------------------------------------------
// K2: circuit simulation.
// Layout: amp physical index p (9 bits): lane = p[8:4], reg slot r = p[3:0].
// Wire w acts on bit 8-w. Per-layer structure: Ry sweep (fast-Givens,
// scale folded into phase table) -> diagonal phase -> CNOT-ring permutation
// (verified R1: new[n]=old[pi(n)], pi: b_j'=b_j^b_{j+1} j<=6, b7'=b7^b8^b0,
// b8'=b8^b0).
// Layer 0 computed ANALYTICALLY (input is basis state e_col): zero shuffles.
// Layers 1-3: re exchanged via SHFL, im via smem (separate HW pipes).
// ---------------------------------------------------------------------------
__global__ __launch_bounds__(512) void k2_sim(float* __restrict__ out) {
    int b    = blockIdx.x >> 5;   // batch
    int grp  = blockIdx.x & 31;   // 32 groups x 16 columns
    int wid  = threadIdx.x >> 5;
    int lane = threadIdx.x & 31;
    int col  = grp * 16 + wid;
    int tid  = threadIdx.x;

    extern __shared__ char dsm[];
    float* gf = (float*)(dsm + SM_GF);                       // 144 floats
    float2 (*ph)[16][32] = (float2 (*)[16][32])(dsm + SM_PH); // [L][r][lane]
    float* exch_all = (float*)(dsm + SM_EXCH);               // 16 x 1024
    float (*tile)[513] = (float (*)[513])exch_all;           // alias (epilogue)

    if (tid < NGATES * 4) gf[tid] = g_coef[b * NGATES * 4 + tid];
    __syncthreads();

    // ---- prologue: per-layer diagonal phase tables ----
    // L0 stored PRE-PERMUTED (at p = pi^{-1}(n)); L1-3 at n, scaled by C_L.
    {
        const int n = tid;
#pragma unroll
        for (int L = 0; L < NLAYERS; L++) {
            float pr = 1.f, pi = 0.f;
#pragma unroll
            for (int w = 0; w < 9; w++) {
                float cp = gf[(L * 9 + w) * 4 + 2];
                float sp = gf[(L * 9 + w) * 4 + 3];
                float sg = ((n >> (8 - w)) & 1) ? sp : -sp;
                float nr = fmaf(pr, cp, -pi * sg);
                float ni = fmaf(pr, sg,  pi * cp);
                pr = nr; pi = ni;
            }
            if (L == 0) {
                // p0 = parity(n); p_{j+1} = n_j ^ p_j (j=0..6); p8 = n8 ^ p0
                int p0 = __popc(n) & 1;
                int p = p0, pj = p0;
#pragma unroll
                for (int j = 0; j < 7; j++) { pj ^= (n >> j) & 1; p |= pj << (j + 1); }
                p |= (((n >> 8) & 1) ^ p0) << 8;
                ph[0][p & 15][p >> 4] = make_float2(pr, pi);
            } else {
                float C = 1.f;
#pragma unroll
                for (int w = 0; w < 9; w++) C *= gf[(L * 9 + w) * 4];
                ph[L][n & 15][n >> 4] = make_float2(C * pr, C * pi);
            }
        }
    }
    __syncthreads();

    const int par  = __popc(lane) & 1;
    const int gl   = lane ^ (lane >> 1);
    const int psrc = __popc(gl) & 1;   // parity of source lane in perm (r-indep)
    const int l0 = lane & 1, l1 = (lane >> 1) & 1, l2 = (lane >> 2) & 1;
    const int l3 = (lane >> 3) & 1, l4 = (lane >> 4) & 1;

    float re[16], im[16];

    // ---- layer 0: analytic. amp(p) = prod_w E_w(n_{8-w}) * phase(pi(p)),
    // n = pi(p). E_w(t) = Ry_w[t, col_{8-w}].
    {
        float E0a, E0b, E1a, E1b, E2a, E2b, E3a, E3b, E4a, E4b;
        float E5a, E5b, E6a, E6b, E7a, E7b, E8a, E8b;
#define MKE(W, A, Bv) { float c_ = gf[(W)*4], s_ = gf[(W)*4+1]; \
        int cb = (col >> (8-(W))) & 1; A = cb ? -s_ : c_; Bv = cb ? c_ : s_; }
        MKE(0, E0a, E0b) MKE(1, E1a, E1b) MKE(2, E2a, E2b)
        MKE(3, E3a, E3b) MKE(4, E4a, E4b) MKE(5, E5a, E5b)
        MKE(6, E6a, E6b) MKE(7, E7a, E7b) MKE(8, E8a, E8b)
#undef MKE
        // lane-only n bits: n4=l0^l1 (wire4), n5=l1^l2 (wire3), n6=l2^l3 (wire2)
        float Plane = ((l0 ^ l1) ? E4b : E4a)
                    * ((l1 ^ l2) ? E3b : E3a)
                    * ((l2 ^ l3) ? E2b : E2a);
        // n3 = r3 ^ l0 (wire5)
        float q3_0 = l0 ? E5b : E5a;
        float q3_1 = l0 ? E5a : E5b;
        // n7 = l3^l4^r0 (wire1), n8 = l4^r0 (wire0)
        int x34 = l3 ^ l4;
        float q78_0 = (x34 ? E1b : E1a) * (l4 ? E0b : E0a);
        float q78_1 = (x34 ? E1a : E1b) * (l4 ? E0a : E0b);
#pragma unroll
        for (int r = 0; r < 16; r++) {
            const int r0 = r & 1, r1 = (r >> 1) & 1, r2 = (r >> 2) & 1, r3 = (r >> 3) & 1;
            float amp = Plane
                      * (r3 ? q3_1 : q3_0)
                      * (r0 ? q78_1 : q78_0)
                      * ((r0 ^ r1) ? E8b : E8a)     // n0 -> wire 8
                      * ((r1 ^ r2) ? E7b : E7a)     // n1 -> wire 7
                      * ((r2 ^ r3) ? E6b : E6a);    // n2 -> wire 6
            float2 p0 = ph[0][r][lane];
            re[r] = amp * p0.x;
            im[r] = amp * p0.y;
        }
    }

    // ---- layers 1..3 ----
    float* wbuf = exch_all + wid * 1024;
    int db = 0;
#pragma unroll 1
    for (int L = 1; L < NLAYERS; L++) {
        const float* gL = gf + L * 36;
        // lane-bit wires 0..4 (fast-Givens; re via shfl, im via smem)
#pragma unroll
        for (int w = 0; w < 5; w++) {
            float c_ = gL[w * 4], s_ = gL[w * 4 + 1];
            float tg = __fdividef(s_, c_);
            const int q = 4 - w;
            float bt = ((lane >> q) & 1) ? tg : -tg;
            float* buf = wbuf + db * 512;
#pragma unroll
            for (int r = 0; r < 16; r++) buf[r * 32 + lane] = im[r];
            __syncwarp();
#pragma unroll
            for (int r = 0; r < 16; r++) {
                float ore = __shfl_xor_sync(0xffffffffu, re[r], 1 << q);
                float oim = buf[r * 32 + (lane ^ (1 << q))];
                re[r] = fmaf(bt, ore, re[r]);
                im[r] = fmaf(bt, oim, im[r]);
            }
            db ^= 1;
        }
        // slot-bit wires 5..8 (fast-Givens, in-register)
#pragma unroll
        for (int w = 5; w < 9; w++) {
            float c_ = gL[w * 4], s_ = gL[w * 4 + 1];
            float tg = __fdividef(s_, c_);
            const int bit = 1 << (8 - w);
#pragma unroll
            for (int r0i = 0; r0i < 16; r0i++) {
                if (r0i & bit) continue;
                const int r1i = r0i | bit;
                float a = re[r0i], bb = re[r1i];
                re[r0i] = fmaf(-tg, bb, a);
                re[r1i] = fmaf( tg, a, bb);
                float ai = im[r0i], bi = im[r1i];
                im[r0i] = fmaf(-tg, bi, ai);
                im[r1i] = fmaf( tg, ai, bi);
            }
        }
        if (L < 3) {
            // full phase (C_L folded in table)
#pragma unroll
            for (int r = 0; r < 16; r++) {
                float2 p = ph[L][r][lane];
                float tr = fmaf(p.x, re[r], -(p.y * im[r]));
                float ti = fmaf(p.y, re[r],  (p.x * im[r]));
                re[r] = tr; im[r] = ti;
            }
            // perm full: re via shfl, im via smem
            float* buf = wbuf + db * 512;
#pragma unroll
            for (int r = 0; r < 16; r++) buf[r * 32 + lane] = im[r];
            __syncwarp();
            float nre[16];
#pragma unroll
            for (int r = 0; r < 16; r++) {
                const int idx = r ^ (r >> 1);
                int src = (r & 1) ? (gl ^ 24) : gl;
                float prv = par ? re[idx ^ 8] : re[idx];
                nre[r] = __shfl_sync(0xffffffffu, prv, src);
            }
#pragma unroll
            for (int r = 0; r < 16; r++) {
                const int idx = r ^ (r >> 1);
                int src = (r & 1) ? (gl ^ 24) : gl;
                im[r] = buf[(idx ^ (psrc << 3)) * 32 + src];
            }
#pragma unroll
            for (int r = 0; r < 16; r++) re[r] = nre[r];
            db ^= 1;
        } else {
            // L3: phase re-only, perm re-only (shfl)
#pragma unroll
            for (int r = 0; r < 16; r++) {
                float2 p = ph[3][r][lane];
                re[r] = fmaf(p.x, re[r], -(p.y * im[r]));
            }
            float nre[16];
#pragma unroll
            for (int r = 0; r < 16; r++) {
                const int idx = r ^ (r >> 1);
                int src = (r & 1) ? (gl ^ 24) : gl;
                float prv = par ? re[idx ^ 8] : re[idx];
                nre[r] = __shfl_sync(0xffffffffu, prv, src);
            }
#pragma unroll
            for (int r = 0; r < 16; r++) re[r] = nre[r];
        }
    }

    // Uv[b][i] += Re(U[i,col]) * v[col] for col in 1..71
    if (col >= 1 && col < PPAR) {
        float vc = 0.01f * g_params[b * PPAR + col];
        float* uv = &g_Uv[b * DDIM];
#pragma unroll
        for (int r = 0; r < 16; r++)
            atomicAdd(&uv[(lane << 4) | r], re[r] * vc);
    }

    __syncthreads();   // exchange buffers dead; reuse as writeback tile

#pragma unroll
    for (int r = 0; r < 16; r++) tile[wid][(lane << 4) | r] = re[r];
    __syncthreads();

    // coalesced write: out[b][j][grp*16 + c]
    float* obase = out + (size_t)b * DDIM * DDIM + grp * 16;
    int c  = tid & 15;
    int j0 = tid >> 4;   // 0..31
#pragma unroll
    for (int k = 0; k < 16; k++) {
        int j = k * 32 + j0;
        obase[(size_t)j * DDIM + c] = tile[c][j];
    }
}

// ---------------------------------------------------------------------------
// K3: rank-2 expm update, touches only columns 0..71. One warp per row.
// ---------------------------------------------------------------------------
__global__ void k3_update(float* __restrict__ out) {
    int gw   = (blockIdx.x * blockDim.x + threadIdx.x) >> 5;
    int lane = threadIdx.x & 31;
    int b = gw >> 9;
    int i = gw & 511;
    if (b >= BATCH) return;

    float* row = out + ((size_t)b * DDIM + i) * DDIM;
    float u0  = row[0];
    float uvi = g_Uv[b * DDIM + i];
    float a1 = g_scal[b * 4 + 0];
    float a2 = g_scal[b * 4 + 1];
    float ct = g_scal[b * 4 + 2];
    float f = fmaf(a1, u0, -a2 * uvi);

#pragma unroll
    for (int jj = 0; jj < 3; jj++) {
        int j = lane + jj * 32;
        if (j >= PPAR) break;
        float val;
        if (j == 0) val = fmaf(u0, ct, -a1 * uvi);
        else        val = fmaf(f, 0.01f * g_params[b * PPAR + j], row[j]);
        row[j] = val;
    }
}

// ---------------------------------------------------------------------------
extern "C" void kernel_launch(void* const* d_in, const int* in_sizes, int n_in,
                              void* d_out, int out_size) {
    const float* t  = (const float*)d_in[0];
    const float* w1 = (const float*)d_in[1];
    const float* b1 = (const float*)d_in[2];
    const float* w2 = (const float*)d_in[3];
    const float* b2 = (const float*)d_in[4];
    float* out = (float*)d_out;

    static int smem_set = 0;
    if (!smem_set) {
        cudaFuncSetAttribute(k2_sim, cudaFuncAttributeMaxDynamicSharedMemorySize,
                             SM_TOTAL);
        smem_set = 1;
    }

    k1_params<<<BATCH, 512>>>(t, w1, b1, w2, b2);
    k2_sim<<<BATCH * 32, 512, SM_TOTAL>>>(out);
    k3_update<<<(BATCH * DDIM) / 8, 256>>>(out);
}

// round 5
// speedup vs baseline: 1.2320x; 1.2320x over previous
#include <cuda_runtime.h>
#include <math.h>

#define NWIRES 9
#define NLAYERS 4
#define DDIM 512
#define BATCH 64
#define PPAR 72
#define NGATES 36
#define EMBED 512

// Scratch (allocation-free: __device__ globals)
__device__ float g_params[BATCH * PPAR];
__device__ float g_coef[BATCH * NGATES * 4];   // c, s, cphi, sphi per gate
__device__ float g_scal[BATCH * 4];            // a1, a2, cos th
__device__ float g_Uv[BATCH * DDIM];

// dynamic smem layout for k2
#define SM_PH   576                      // float2 ph[4][512] = 16384 B
#define SM_BUF  17024                    // 16 warps x 1024 floats = 65536 B
#define SM_TOTAL (17024 + 65536)

// ---------------------------------------------------------------------------
// K1: MLP -> params, gate trig coefficients, rank-2 scalars, zero Uv
// ---------------------------------------------------------------------------
__global__ __launch_bounds__(512) void k1_params(
        const float* __restrict__ t, const float* __restrict__ w1,
        const float* __restrict__ b1, const float* __restrict__ w2,
        const float* __restrict__ b2) {
    int b = blockIdx.x;
    int tid = threadIdx.x;
    int w = tid >> 5, lane = tid & 31;
    __shared__ float h[EMBED];
    __shared__ float p[PPAR];

    float tv = t[b];
    {
        float x = fmaf(tv, w1[tid], b1[tid]);
        h[tid] = x / (1.f + expf(-x));   // silu
    }
    if (tid < PPAR) p[tid] = 0.f;
    __syncthreads();

    float a0 = 0.f, a1v = 0.f, a2v = 0.f;
    const float* w2base = w2 + (w * 32) * PPAR;
#pragma unroll 8
    for (int k = 0; k < 32; k++) {
        float hv = h[w * 32 + k];
        const float* row = w2base + k * PPAR;
        a0  = fmaf(hv, row[lane], a0);
        a1v = fmaf(hv, row[lane + 32], a1v);
        if (lane < 8) a2v = fmaf(hv, row[lane + 64], a2v);
    }
    atomicAdd(&p[lane], a0);
    atomicAdd(&p[lane + 32], a1v);
    if (lane < 8) atomicAdd(&p[lane + 64], a2v);
    __syncthreads();

    if (tid < PPAR) {
        float v = p[tid] + b2[tid];
        p[tid] = v;
        g_params[b * PPAR + tid] = v;
    }
    g_Uv[b * DDIM + tid] = 0.f;
    __syncthreads();

    if (tid < NGATES) {
        float thy = p[2 * tid], thz = p[2 * tid + 1];
        float* dst = &g_coef[(b * NGATES + tid) * 4];
        dst[0] = cosf(0.5f * thy);
        dst[1] = sinf(0.5f * thy);
        dst[2] = cosf(0.5f * thz);
        dst[3] = sinf(0.5f * thz);
    }
    if (tid == 0) {
        float s2 = 0.f;
        for (int j = 1; j < PPAR; j++) { float vj = 0.01f * p[j]; s2 = fmaf(vj, vj, s2); }
        float th = sqrtf(s2);
        float ct = cosf(th);
        float a1, a2;
        if (th > 1e-6f) { a1 = sinf(th) / th; a2 = (1.f - ct) / s2; }
        else            { a1 = 1.f - s2 * (1.f / 6.f); a2 = 0.5f; }
        g_scal[b * 4 + 0] = a1;
        g_scal[b * 4 + 1] = a2;
        g_scal[b * 4 + 2] = ct;
    }
}

// CNOT-ring permutation (verified R1): new[n] = old[pi(n)]
// pi: b_j' = b_j^b_{j+1} (j=0..6), b7' = b7^b8^b0, b8' = b8^b0
__device__ __forceinline__ int cperm(int p) {
    int n = (p ^ (p >> 1)) & 0x7F;
    n |= (((p >> 7) ^ (p >> 8) ^ p) & 1) << 7;
    n |= (((p >> 8) ^ p) & 1) << 8;
    return n;
}
// swizzles (GF(2)-rank-verified conflict-free for their access patterns)
__device__ __forceinline__ int f2s(int a) {
    return a ^ ((a >> 5) & 15) ^ ((a >> 4) & 16);
}

// ---------------------------------------------------------------------------
// K2: circuit simulation. One column per warp.
// Layout A: amp p -> lane=p[8:4], slot=p[3:0]  (wires 5-8 register-local)
// Layout B: amp p -> lane=p[4:0], slot=p[8:5]  (wires 0-3 register-local;
//           wire 4 = lane-bit-4 shfl gate)
// Per layer: [A gates] -> transpose A->B (f1) -> [B gates + phase] ->
//            transpose B->A with CNOT perm folded into read addrs (f2).
// Layer 0 analytic (basis-state input, validated R4). Fast-Givens with the
// per-layer scale prod(c) folded into the phase tables.
// ---------------------------------------------------------------------------
__global__ __launch_bounds__(512) void k2_sim(float* __restrict__ out) {
    int b    = blockIdx.x >> 5;   // batch
    int grp  = blockIdx.x & 31;   // 32 groups x 16 columns
    int wid  = threadIdx.x >> 5;
    int lane = threadIdx.x & 31;
    int col  = grp * 16 + wid;
    int tid  = threadIdx.x;

    extern __shared__ char dsm[];
    float*  gf  = (float*)dsm;                    // 144 floats
    float2* ph  = (float2*)(dsm + SM_PH);         // [4][512]
    float*  buf = (float*)(dsm + SM_BUF);         // 16 x 1024 floats
    float (*tile)[513] = (float (*)[513])buf;     // epilogue alias

    if (tid < NGATES * 4) gf[tid] = g_coef[b * NGATES * 4 + tid];
    __syncthreads();

    // ---- prologue: per-layer diagonal phase tables ----
    // L0 stored pre-permuted & transposed (layout-A index of p=pi^{-1}(n));
    // L1-3 stored at linear n (layout-B read: n=(s<<5)|lane), scaled by C_L.
    {
        const int n = tid;
#pragma unroll
        for (int L = 0; L < NLAYERS; L++) {
            float pr = 1.f, pi = 0.f;
#pragma unroll
            for (int w = 0; w < 9; w++) {
                float cp = gf[(L * 9 + w) * 4 + 2];
                float sp = gf[(L * 9 + w) * 4 + 3];
                float sg = ((n >> (8 - w)) & 1) ? sp : -sp;
                float nr = fmaf(pr, cp, -pi * sg);
                float ni = fmaf(pr, sg,  pi * cp);
                pr = nr; pi = ni;
            }
            if (L == 0) {
                // p0 = parity(n); p_{j+1} = n_j ^ p_j (j=0..6); p8 = n8 ^ p0
                int p0 = __popc(n) & 1;
                int p = p0, pj = p0;
#pragma unroll
                for (int j = 0; j < 7; j++) { pj ^= (n >> j) & 1; p |= pj << (j + 1); }
                p |= (((n >> 8) & 1) ^ p0) << 8;
                ph[((p & 15) << 5) | (p >> 4)] = make_float2(pr, pi);
            } else {
                float C = 1.f;
#pragma unroll
                for (int w = 0; w < 9; w++) C *= gf[(L * 9 + w) * 4];
                ph[L * 512 + n] = make_float2(C * pr, C * pi);
            }
        }
    }
    __syncthreads();

    const int l0 = lane & 1, l1 = (lane >> 1) & 1, l2 = (lane >> 2) & 1;
    const int l3 = (lane >> 3) & 1, l4 = (lane >> 4) & 1;

    float re[16], im[16];

    // ---- layer 0: analytic (validated R4) ----
    {
        float E0a, E0b, E1a, E1b, E2a, E2b, E3a, E3b, E4a, E4b;
        float E5a, E5b, E6a, E6b, E7a, E7b, E8a, E8b;
#define MKE(W, A, Bv) { float c_ = gf[(W)*4], s_ = gf[(W)*4+1]; \
        int cb = (col >> (8-(W))) & 1; A = cb ? -s_ : c_; Bv = cb ? c_ : s_; }
        MKE(0, E0a, E0b) MKE(1, E1a, E1b) MKE(2, E2a, E2b)
        MKE(3, E3a, E3b) MKE(4, E4a, E4b) MKE(5, E5a, E5b)
        MKE(6, E6a, E6b) MKE(7, E7a, E7b) MKE(8, E8a, E8b)
#undef MKE
        float Plane = ((l0 ^ l1) ? E4b : E4a)
                    * ((l1 ^ l2) ? E3b : E3a)
                    * ((l2 ^ l3) ? E2b : E2a);
        float q3_0 = l0 ? E5b : E5a;
        float q3_1 = l0 ? E5a : E5b;
        int x34 = l3 ^ l4;
        float q78_0 = (x34 ? E1b : E1a) * (l4 ? E0b : E0a);
        float q78_1 = (x34 ? E1a : E1b) * (l4 ? E0a : E0b);
#pragma unroll
        for (int r = 0; r < 16; r++) {
            const int r0 = r & 1, r1 = (r >> 1) & 1, r2 = (r >> 2) & 1, r3 = (r >> 3) & 1;
            float amp = Plane
                      * (r3 ? q3_1 : q3_0)
                      * (r0 ? q78_1 : q78_0)
                      * ((r0 ^ r1) ? E8b : E8a)
                      * ((r1 ^ r2) ? E7b : E7a)
                      * ((r2 ^ r3) ? E6b : E6a);
            float2 p0 = ph[(r << 5) | lane];
            re[r] = amp * p0.x;
            im[r] = amp * p0.y;
        }
    }

    // precomputed exchange addresses
    float* wbr = buf + wid * 1024;          // re buffer (512)
    float* wbi = wbr + 512;                 // im buffer (512)
    const int awb = (lane << 4) ^ lane;             // A-write: addr = awb ^ r
    const int lb  = lane ^ (lane >> 4);             // B-read:  addr = s*34 ^ lb
    int pa[16];                                     // B->A perm-folded read
#pragma unroll
    for (int r = 0; r < 16; r++) pa[r] = f2s(cperm((lane << 4) | r));

#pragma unroll 1
    for (int L = 1; L < NLAYERS; L++) {
        const float* gL = gf + L * 36;
        // ---- layout A: wires 5..8 (slot bits 3..0), fast-Givens ----
#pragma unroll
        for (int w = 5; w < 9; w++) {
            float tg = __fdividef(gL[w * 4 + 1], gL[w * 4]);
            const int bit = 1 << (8 - w);
#pragma unroll
            for (int r0i = 0; r0i < 16; r0i++) {
                if (r0i & bit) continue;
                const int r1i = r0i | bit;
                float a = re[r0i], bb = re[r1i];
                re[r0i] = fmaf(-tg, bb, a);
                re[r1i] = fmaf( tg, a, bb);
                float ai = im[r0i], bi = im[r1i];
                im[r0i] = fmaf(-tg, bi, ai);
                im[r1i] = fmaf( tg, ai, bi);
            }
        }
        // ---- transpose A->B (swizzle f1(a)=a^(a>>4)) ----
#pragma unroll
        for (int r = 0; r < 16; r++) {
            int a = awb ^ r;
            wbr[a] = re[r]; wbi[a] = im[r];
        }
        __syncwarp();
#pragma unroll
        for (int s = 0; s < 16; s++) {
            int a = (s * 34) ^ lb;
            re[s] = wbr[a]; im[s] = wbi[a];
        }
        __syncwarp();
        // ---- layout B: wires 0..3 (slot bits 3..0 of s = p[8:5]) ----
#pragma unroll
        for (int w = 0; w < 4; w++) {
            float tg = __fdividef(gL[w * 4 + 1], gL[w * 4]);
            const int bit = 1 << (3 - w);
#pragma unroll
            for (int s0 = 0; s0 < 16; s0++) {
                if (s0 & bit) continue;
                const int s1 = s0 | bit;
                float a = re[s0], bb = re[s1];
                re[s0] = fmaf(-tg, bb, a);
                re[s1] = fmaf( tg, a, bb);
                float ai = im[s0], bi = im[s1];
                im[s0] = fmaf(-tg, bi, ai);
                im[s1] = fmaf( tg, ai, bi);
            }
        }
        // ---- wire 4: lane bit 4 (shfl gate) ----
        {
            float tg = __fdividef(gL[4 * 4 + 1], gL[4 * 4]);
            float bt = l4 ? tg : -tg;
#pragma unroll
            for (int s = 0; s < 16; s++) {
                float ore = __shfl_xor_sync(0xffffffffu, re[s], 16);
                float oim = __shfl_xor_sync(0xffffffffu, im[s], 16);
                re[s] = fmaf(bt, ore, re[s]);
                im[s] = fmaf(bt, oim, im[s]);
            }
        }
        if (L < 3) {
            // ---- phase (C_L folded), layout B: n = (s<<5)|lane ----
            const float2* phL = ph + L * 512;
#pragma unroll
            for (int s = 0; s < 16; s++) {
                float2 pq = phL[(s << 5) | lane];
                float tr = fmaf(pq.x, re[s], -(pq.y * im[s]));
                float ti = fmaf(pq.y, re[s],  (pq.x * im[s]));
                re[s] = tr; im[s] = ti;
            }
            // ---- transpose B->A with perm folded (swizzle f2) ----
#pragma unroll
            for (int s = 0; s < 16; s++) {
                int a = ((s << 5) ^ (s & 15) ^ ((s & 8) << 1)) ^ lane;
                wbr[a] = re[s]; wbi[a] = im[s];
            }
            __syncwarp();
#pragma unroll
            for (int r = 0; r < 16; r++) {
                re[r] = wbr[pa[r]];
                im[r] = wbi[pa[r]];
            }
            __syncwarp();
        } else {
            // ---- L3: phase re-only, transpose re-only ----
            const float2* phL = ph + 3 * 512;
#pragma unroll
            for (int s = 0; s < 16; s++) {
                float2 pq = phL[(s << 5) | lane];
                re[s] = fmaf(pq.x, re[s], -(pq.y * im[s]));
            }
#pragma unroll
            for (int s = 0; s < 16; s++) {
                int a = ((s << 5) ^ (s & 15) ^ ((s & 8) << 1)) ^ lane;
                wbr[a] = re[s];
            }
            __syncwarp();
#pragma unroll
            for (int r = 0; r < 16; r++) re[r] = wbr[pa[r]];
            __syncwarp();
        }
    }

    // Uv[b][i] += Re(U[i,col]) * v[col] for col in 1..71
    if (col >= 1 && col < PPAR) {
        float vc = 0.01f * g_params[b * PPAR + col];
        float* uv = &g_Uv[b * DDIM];
#pragma unroll
        for (int r = 0; r < 16; r++)
            atomicAdd(&uv[(lane << 4) | r], re[r] * vc);
    }

    __syncthreads();   // all warps done with exchange buffers; alias as tile

#pragma unroll
    for (int r = 0; r < 16; r++) tile[wid][(lane << 4) | r] = re[r];
    __syncthreads();

    // coalesced write: out[b][j][grp*16 + c]
    float* obase = out + (size_t)b * DDIM * DDIM + grp * 16;
    int c  = tid & 15;
    int j0 = tid >> 4;   // 0..31
#pragma unroll
    for (int k = 0; k < 16; k++) {
        int j = k * 32 + j0;
        obase[(size_t)j * DDIM + c] = tile[c][j];
    }
}

// ---------------------------------------------------------------------------
// K3: rank-2 expm update, touches only columns 0..71. One warp per row.
// ---------------------------------------------------------------------------
__global__ void k3_update(float* __restrict__ out) {
    int gw   = (blockIdx.x * blockDim.x + threadIdx.x) >> 5;
    int lane = threadIdx.x & 31;
    int b = gw >> 9;
    int i = gw & 511;
    if (b >= BATCH) return;

    float* row = out + ((size_t)b * DDIM + i) * DDIM;
    float u0  = row[0];
    float uvi = g_Uv[b * DDIM + i];
    float a1 = g_scal[b * 4 + 0];
    float a2 = g_scal[b * 4 + 1];
    float ct = g_scal[b * 4 + 2];
    float f = fmaf(a1, u0, -a2 * uvi);

#pragma unroll
    for (int jj = 0; jj < 3; jj++) {
        int j = lane + jj * 32;
        if (j >= PPAR) break;
        float val;
        if (j == 0) val = fmaf(u0, ct, -a1 * uvi);
        else        val = fmaf(f, 0.01f * g_params[b * PPAR + j], row[j]);
        row[j] = val;
    }
}

// ---------------------------------------------------------------------------
extern "C" void kernel_launch(void* const* d_in, const int* in_sizes, int n_in,
                              void* d_out, int out_size) {
    const float* t  = (const float*)d_in[0];
    const float* w1 = (const float*)d_in[1];
    const float* b1 = (const float*)d_in[2];
    const float* w2 = (const float*)d_in[3];
    const float* b2 = (const float*)d_in[4];
    float* out = (float*)d_out;

    static int smem_set = 0;
    if (!smem_set) {
        cudaFuncSetAttribute(k2_sim, cudaFuncAttributeMaxDynamicSharedMemorySize,
                             SM_TOTAL);
        smem_set = 1;
    }

    k1_params<<<BATCH, 512>>>(t, w1, b1, w2, b2);
    k2_sim<<<BATCH * 32, 512, SM_TOTAL>>>(out);
    k3_update<<<(BATCH * DDIM) / 8, 256>>>(out);
}

// round 8
// speedup vs baseline: 1.3721x; 1.1137x over previous
#include <cuda_runtime.h>
#include <math.h>

#define NWIRES 9
#define NLAYERS 4
#define DDIM 512
#define BATCH 64
#define PPAR 72
#define NGATES 36
#define EMBED 512

// Scratch (allocation-free: __device__ globals)
__device__ float g_params[BATCH * PPAR];
__device__ float g_coef[BATCH * NGATES * 4];   // c, s, cphi, sphi per gate
__device__ float g_scal[BATCH * 4];            // a1, a2, cos th
__device__ float g_Uv[BATCH * DDIM];

// dynamic smem layout for k2
#define SM_PH   576                      // float2 ph[4][512] = 16384 B
#define SM_BUF  17024                    // 16 warps x 512 float2 = 65536 B
#define SM_TOTAL (17024 + 65536)

// ---------------------------------------------------------------------------
// K1: MLP -> params, gate trig coefficients, rank-2 scalars, zero Uv
// ---------------------------------------------------------------------------
__global__ __launch_bounds__(512) void k1_params(
        const float* __restrict__ t, const float* __restrict__ w1,
        const float* __restrict__ b1, const float* __restrict__ w2,
        const float* __restrict__ b2) {
    int b = blockIdx.x;
    int tid = threadIdx.x;
    int w = tid >> 5, lane = tid & 31;
    __shared__ float h[EMBED];
    __shared__ float p[PPAR];

    float tv = t[b];
    {
        float x = fmaf(tv, w1[tid], b1[tid]);
        h[tid] = x / (1.f + expf(-x));   // silu
    }
    if (tid < PPAR) p[tid] = 0.f;
    __syncthreads();

    float a0 = 0.f, a1v = 0.f, a2v = 0.f;
    const float* w2base = w2 + (w * 32) * PPAR;
#pragma unroll 8
    for (int k = 0; k < 32; k++) {
        float hv = h[w * 32 + k];
        const float* row = w2base + k * PPAR;
        a0  = fmaf(hv, row[lane], a0);
        a1v = fmaf(hv, row[lane + 32], a1v);
        if (lane < 8) a2v = fmaf(hv, row[lane + 64], a2v);
    }
    atomicAdd(&p[lane], a0);
    atomicAdd(&p[lane + 32], a1v);
    if (lane < 8) atomicAdd(&p[lane + 64], a2v);
    __syncthreads();

    if (tid < PPAR) {
        float v = p[tid] + b2[tid];
        p[tid] = v;
        g_params[b * PPAR + tid] = v;
    }
    g_Uv[b * DDIM + tid] = 0.f;
    __syncthreads();

    if (tid < NGATES) {
        float thy = p[2 * tid], thz = p[2 * tid + 1];
        float* dst = &g_coef[(b * NGATES + tid) * 4];
        dst[0] = cosf(0.5f * thy);
        dst[1] = sinf(0.5f * thy);
        dst[2] = cosf(0.5f * thz);
        dst[3] = sinf(0.5f * thz);
    }
    if (tid == 0) {
        float s2 = 0.f;
        for (int j = 1; j < PPAR; j++) { float vj = 0.01f * p[j]; s2 = fmaf(vj, vj, s2); }
        float th = sqrtf(s2);
        float ct = cosf(th);
        float a1, a2;
        if (th > 1e-6f) { a1 = sinf(th) / th; a2 = (1.f - ct) / s2; }
        else            { a1 = 1.f - s2 * (1.f / 6.f); a2 = 0.5f; }
        g_scal[b * 4 + 0] = a1;
        g_scal[b * 4 + 1] = a2;
        g_scal[b * 4 + 2] = ct;
    }
}

// CNOT-ring permutation (verified R1): new[n] = old[pi(n)]
__device__ __forceinline__ int cperm(int p) {
    int n = (p ^ (p >> 1)) & 0x7F;
    n |= (((p >> 7) ^ (p >> 8) ^ p) & 1) << 7;
    n |= (((p >> 8) ^ p) & 1) << 8;
    return n;
}
// B->A swizzle (GF(2)-rank-verified conflict-free, scalar AND float2 banks)
__device__ __forceinline__ int f2s(int a) {
    return a ^ ((a >> 5) & 15) ^ ((a >> 4) & 16);
}

// ---------------------------------------------------------------------------
// K2: circuit simulation. One column per warp.
// Layout A: lane=p[8:4], slot=p[3:0] (wires 5-8 register-local)
// Layout B: lane=p[4:0], slot=p[8:5] (wires 0-3 register-local; wire 4 shfl)
// Per layer: [A gates] -> transpose A->B (swizzle x^(x>>4)) ->
//            [B gates + wire4 + phase] -> transpose B->A with the
//            CNOT-ring perm folded into read addressing (swizzle f2s).
// Transposes move {re,im} as float2 (STS.64/LDS.64, conflict-free).
// pa[r] = f2s(cperm(lane<<4)) ^ f2s(cperm(r)) by GF(2) linearity
// (R6 bug: cperm(lane<<4) is NOT lane*24; now computed exactly).
// ---------------------------------------------------------------------------
__global__ __launch_bounds__(512, 2) void k2_sim(float* __restrict__ out) {
    int b    = blockIdx.x >> 5;   // batch
    int grp  = blockIdx.x & 31;   // 32 groups x 16 columns
    int wid  = threadIdx.x >> 5;
    int lane = threadIdx.x & 31;
    int col  = grp * 16 + wid;
    int tid  = threadIdx.x;

    extern __shared__ char dsm[];
    float*  gf  = (float*)dsm;                    // 144 floats
    float2* ph  = (float2*)(dsm + SM_PH);         // [4][512]
    float2* buf2 = (float2*)(dsm + SM_BUF);       // 16 warps x 512 float2
    float (*tile)[513] = (float (*)[513])buf2;    // epilogue alias

    if (tid < NGATES * 4) gf[tid] = g_coef[b * NGATES * 4 + tid];
    __syncthreads();

    // ---- prologue: per-layer diagonal phase tables ----
    {
        const int n = tid;
#pragma unroll
        for (int L = 0; L < NLAYERS; L++) {
            float pr = 1.f, pi = 0.f;
#pragma unroll
            for (int w = 0; w < 9; w++) {
                float cp = gf[(L * 9 + w) * 4 + 2];
                float sp = gf[(L * 9 + w) * 4 + 3];
                float sg = ((n >> (8 - w)) & 1) ? sp : -sp;
                float nr = fmaf(pr, cp, -pi * sg);
                float ni = fmaf(pr, sg,  pi * cp);
                pr = nr; pi = ni;
            }
            if (L == 0) {
                // stored pre-permuted (at p = pi^{-1}(n)), layout-A index
                int p0 = __popc(n) & 1;
                int p = p0, pj = p0;
#pragma unroll
                for (int j = 0; j < 7; j++) { pj ^= (n >> j) & 1; p |= pj << (j + 1); }
                p |= (((n >> 8) & 1) ^ p0) << 8;
                ph[((p & 15) << 5) | (p >> 4)] = make_float2(pr, pi);
            } else {
                float C = 1.f;
#pragma unroll
                for (int w = 0; w < 9; w++) C *= gf[(L * 9 + w) * 4];
                ph[L * 512 + n] = make_float2(C * pr, C * pi);
            }
        }
    }
    __syncthreads();

    const int l0 = lane & 1, l1 = (lane >> 1) & 1, l2 = (lane >> 2) & 1;
    const int l3 = (lane >> 3) & 1, l4 = (lane >> 4) & 1;

    float re[16], im[16];

    // ---- layer 0: analytic (validated R4/R5) ----
    {
        float E0a, E0b, E1a, E1b, E2a, E2b, E3a, E3b, E4a, E4b;
        float E5a, E5b, E6a, E6b, E7a, E7b, E8a, E8b;
#define MKE(W, A, Bv) { float c_ = gf[(W)*4], s_ = gf[(W)*4+1]; \
        int cb = (col >> (8-(W))) & 1; A = cb ? -s_ : c_; Bv = cb ? c_ : s_; }
        MKE(0, E0a, E0b) MKE(1, E1a, E1b) MKE(2, E2a, E2b)
        MKE(3, E3a, E3b) MKE(4, E4a, E4b) MKE(5, E5a, E5b)
        MKE(6, E6a, E6b) MKE(7, E7a, E7b) MKE(8, E8a, E8b)
#undef MKE
        float Plane = ((l0 ^ l1) ? E4b : E4a)
                    * ((l1 ^ l2) ? E3b : E3a)
                    * ((l2 ^ l3) ? E2b : E2a);
        float q3_0 = l0 ? E5b : E5a;
        float q3_1 = l0 ? E5a : E5b;
        int x34 = l3 ^ l4;
        float q78_0 = (x34 ? E1b : E1a) * (l4 ? E0b : E0a);
        float q78_1 = (x34 ? E1a : E1b) * (l4 ? E0a : E0b);
#pragma unroll
        for (int r = 0; r < 16; r++) {
            const int r0 = r & 1, r1 = (r >> 1) & 1, r2 = (r >> 2) & 1, r3 = (r >> 3) & 1;
            float amp = Plane
                      * (r3 ? q3_1 : q3_0)
                      * (r0 ? q78_1 : q78_0)
                      * ((r0 ^ r1) ? E8b : E8a)
                      * ((r1 ^ r2) ? E7b : E7a)
                      * ((r2 ^ r3) ? E6b : E6a);
            float2 p0 = ph[(r << 5) | lane];
            re[r] = amp * p0.x;
            im[r] = amp * p0.y;
        }
    }

    // exchange addressing (all verified conflict-free, all <= 511)
    float2* wb = buf2 + wid * 512;
    float*  wbF = (float*)wb;                   // scalar view (L3)
    const int awb = (lane << 4) ^ lane;         // A-write: addr = awb ^ r
    const int lb  = lane ^ (lane >> 4);         // B-read:  addr = s*34 ^ lb
    const int pwb = lane;                       // B-write: addr = pwb ^ sconst
    const int paBase = f2s(cperm(lane << 4));   // exact (R6 fix)

#pragma unroll 1
    for (int L = 1; L < NLAYERS; L++) {
        const float* gL = gf + L * 36;
        // ---- layout A: wires 5..8, fast-Givens ----
#pragma unroll
        for (int w = 5; w < 9; w++) {
            float tg = __fdividef(gL[w * 4 + 1], gL[w * 4]);
            const int bit = 1 << (8 - w);
#pragma unroll
            for (int r0i = 0; r0i < 16; r0i++) {
                if (r0i & bit) continue;
                const int r1i = r0i | bit;
                float a = re[r0i], bb = re[r1i];
                re[r0i] = fmaf(-tg, bb, a);
                re[r1i] = fmaf( tg, a, bb);
                float ai = im[r0i], bi = im[r1i];
                im[r0i] = fmaf(-tg, bi, ai);
                im[r1i] = fmaf( tg, ai, bi);
            }
        }
        // ---- transpose A->B (float2, swizzle x^(x>>4)) ----
#pragma unroll
        for (int r = 0; r < 16; r++) wb[awb ^ r] = make_float2(re[r], im[r]);
        __syncwarp();
#pragma unroll
        for (int s = 0; s < 16; s++) {
            float2 v = wb[(s * 34) ^ lb];
            re[s] = v.x; im[s] = v.y;
        }
        __syncwarp();
        // ---- layout B: wires 0..3 ----
#pragma unroll
        for (int w = 0; w < 4; w++) {
            float tg = __fdividef(gL[w * 4 + 1], gL[w * 4]);
            const int bit = 1 << (3 - w);
#pragma unroll
            for (int s0 = 0; s0 < 16; s0++) {
                if (s0 & bit) continue;
                const int s1 = s0 | bit;
                float a = re[s0], bb = re[s1];
                re[s0] = fmaf(-tg, bb, a);
                re[s1] = fmaf( tg, a, bb);
                float ai = im[s0], bi = im[s1];
                im[s0] = fmaf(-tg, bi, ai);
                im[s1] = fmaf( tg, ai, bi);
            }
        }
        // ---- wire 4: lane bit 4 (shfl) ----
        {
            float tg = __fdividef(gL[4 * 4 + 1], gL[4 * 4]);
            float bt = l4 ? tg : -tg;
#pragma unroll
            for (int s = 0; s < 16; s++) {
                float ore = __shfl_xor_sync(0xffffffffu, re[s], 16);
                float oim = __shfl_xor_sync(0xffffffffu, im[s], 16);
                re[s] = fmaf(bt, ore, re[s]);
                im[s] = fmaf(bt, oim, im[s]);
            }
        }
        if (L < 3) {
            // ---- phase (C_L folded), layout B: n = (s<<5)|lane ----
            const float2* phL = ph + L * 512;
#pragma unroll
            for (int s = 0; s < 16; s++) {
                float2 pq = phL[(s << 5) | lane];
                float tr = fmaf(pq.x, re[s], -(pq.y * im[s]));
                float ti = fmaf(pq.y, re[s],  (pq.x * im[s]));
                re[s] = tr; im[s] = ti;
            }
            // ---- transpose B->A with perm folded (float2, swizzle f2s) ----
#pragma unroll
            for (int s = 0; s < 16; s++) {
                int a = ((s << 5) ^ (s & 15) ^ ((s & 8) << 1)) ^ pwb;
                wb[a] = make_float2(re[s], im[s]);
            }
            __syncwarp();
#pragma unroll
            for (int r = 0; r < 16; r++) {
                float2 v = wb[paBase ^ f2s(cperm(r))];   // const-folded per r
                re[r] = v.x; im[r] = v.y;
            }
            __syncwarp();
        } else {
            // ---- L3: phase re-only, scalar re-only transpose ----
            const float2* phL = ph + 3 * 512;
#pragma unroll
            for (int s = 0; s < 16; s++) {
                float2 pq = phL[(s << 5) | lane];
                re[s] = fmaf(pq.x, re[s], -(pq.y * im[s]));
            }
#pragma unroll
            for (int s = 0; s < 16; s++) {
                int a = ((s << 5) ^ (s & 15) ^ ((s & 8) << 1)) ^ pwb;
                wbF[a] = re[s];
            }
            __syncwarp();
#pragma unroll
            for (int r = 0; r < 16; r++)
                re[r] = wbF[paBase ^ f2s(cperm(r))];
            __syncwarp();
        }
    }

    // Uv[b][i] += Re(U[i,col]) * v[col] for col in 1..71
    if (col >= 1 && col < PPAR) {
        float vc = 0.01f * g_params[b * PPAR + col];
        float* uv = &g_Uv[b * DDIM];
#pragma unroll
        for (int r = 0; r < 16; r++)
            atomicAdd(&uv[(lane << 4) | r], re[r] * vc);
    }

    __syncthreads();   // all warps done with exchange buffers; alias as tile

#pragma unroll
    for (int r = 0; r < 16; r++) tile[wid][(lane << 4) | r] = re[r];
    __syncthreads();

    // coalesced write: out[b][j][grp*16 + c]
    float* obase = out + (size_t)b * DDIM * DDIM + grp * 16;
    int c  = tid & 15;
    int j0 = tid >> 4;   // 0..31
#pragma unroll
    for (int k = 0; k < 16; k++) {
        int j = k * 32 + j0;
        obase[(size_t)j * DDIM + c] = tile[c][j];
    }
}

// ---------------------------------------------------------------------------
// K3: rank-2 expm update, touches only columns 0..71. One warp per row.
// ---------------------------------------------------------------------------
__global__ void k3_update(float* __restrict__ out) {
    int gw   = (blockIdx.x * blockDim.x + threadIdx.x) >> 5;
    int lane = threadIdx.x & 31;
    int b = gw >> 9;
    int i = gw & 511;
    if (b >= BATCH) return;

    float* row = out + ((size_t)b * DDIM + i) * DDIM;
    float u0  = row[0];
    float uvi = g_Uv[b * DDIM + i];
    float a1 = g_scal[b * 4 + 0];
    float a2 = g_scal[b * 4 + 1];
    float ct = g_scal[b * 4 + 2];
    float f = fmaf(a1, u0, -a2 * uvi);

#pragma unroll
    for (int jj = 0; jj < 3; jj++) {
        int j = lane + jj * 32;
        if (j >= PPAR) break;
        float val;
        if (j == 0) val = fmaf(u0, ct, -a1 * uvi);
        else        val = fmaf(f, 0.01f * g_params[b * PPAR + j], row[j]);
        row[j] = val;
    }
}

// ---------------------------------------------------------------------------
extern "C" void kernel_launch(void* const* d_in, const int* in_sizes, int n_in,
                              void* d_out, int out_size) {
    const float* t  = (const float*)d_in[0];
    const float* w1 = (const float*)d_in[1];
    const float* b1 = (const float*)d_in[2];
    const float* w2 = (const float*)d_in[3];
    const float* b2 = (const float*)d_in[4];
    float* out = (float*)d_out;

    static int smem_set = 0;
    if (!smem_set) {
        cudaFuncSetAttribute(k2_sim, cudaFuncAttributeMaxDynamicSharedMemorySize,
                             SM_TOTAL);
        smem_set = 1;
    }

    k1_params<<<BATCH, 512>>>(t, w1, b1, w2, b2);
    k2_sim<<<BATCH * 32, 512, SM_TOTAL>>>(out);
    k3_update<<<(BATCH * DDIM) / 8, 256>>>(out);
}

// round 13
// speedup vs baseline: 1.4928x; 1.0879x over previous
#include <cuda_runtime.h>
#include <math.h>

#define NWIRES 9
#define NLAYERS 4
#define DDIM 512
#define BATCH 64
#define PPAR 72
#define NGATES 36
#define EMBED 512

// Scratch (allocation-free)
__device__ float g_params[BATCH * PPAR];

// dynamic smem layout for the sim kernel
#define SM_GF   0                        // 144 floats
#define SM_PLO  576                      // float2[4][32]
#define SM_PHI  1600                     // float2[4][16]
#define SM_PP   2112                     // 80 floats (params accum)
#define SM_PH   2560                     // float2[4][512] = 16384 B
#define SM_BUF  18944                    // 16 warps x 512 float2 = 65536 B
#define SM_TOTAL (18944 + 65536)

// CNOT-ring permutation (verified R1): new[n] = old[pi(n)]
__device__ __forceinline__ int cperm(int p) {
    int n = (p ^ (p >> 1)) & 0x7F;
    n |= (((p >> 7) ^ (p >> 8) ^ p) & 1) << 7;
    n |= (((p >> 8) ^ p) & 1) << 8;
    return n;
}
// inverse of cperm (GF(2)-linear; validated as the L0 pre-permute map R4-R8)
__device__ __forceinline__ int pinv9(int n) {
    int pb = __popc(n) & 1;
    int acc = pb, run = pb;
#pragma unroll
    for (int j = 0; j < 7; j++) { run ^= (n >> j) & 1; acc |= run << (j + 1); }
    acc |= (((n >> 8) & 1) ^ pb) << 8;
    return acc;
}
// B->A swizzle (GF(2)-rank-verified conflict-free)
__device__ __forceinline__ int f2s(int a) {
    return a ^ ((a >> 5) & 15) ^ ((a >> 4) & 16);
}

// ---------------------------------------------------------------------------
// Sim kernel: fused MLP + circuit simulation. One column per warp.
// Layout A: lane=p[8:4], slot=p[3:0] (wires 5-8 register-local)
// Layout B: lane=p[4:0], slot=p[8:5] (wires 0-3 register-local; wire 4 shfl)
// Per layer: [A gates] -> transpose A->B -> [B gates + wire4 + phase] ->
//            transpose B->A with CNOT perm folded (L1/L2); L3 keeps layout B
//            and folds the perm into the tile-store addressing via pinv9.
// Phase tables factorized: ph(n) = plo(n&31)*phi(n>>5); C_L folded into phi.
// L0 table stored at the LAYOUT-A index of p=pinv9(n)  (the R9 bugfix).
// ---------------------------------------------------------------------------
__global__ __launch_bounds__(512, 2) void k2_sim(
        float* __restrict__ out,
        const float* __restrict__ t,  const float* __restrict__ w1,
        const float* __restrict__ b1, const float* __restrict__ w2,
        const float* __restrict__ b2) {
    const int b    = blockIdx.x >> 5;   // batch
    const int grp  = blockIdx.x & 31;   // 32 groups x 16 columns
    const int wid  = threadIdx.x >> 5;
    const int lane = threadIdx.x & 31;
    const int col  = grp * 16 + wid;
    const int tid  = threadIdx.x;

    extern __shared__ char dsm[];
    float*  gf   = (float*)(dsm + SM_GF);          // 36 gates x {c,s,cp,sp}
    float2* plo  = (float2*)(dsm + SM_PLO);        // [4][32]
    float2* phi  = (float2*)(dsm + SM_PHI);        // [4][16]
    float*  pp   = (float*)(dsm + SM_PP);          // params accum
    float2* ph   = (float2*)(dsm + SM_PH);         // [4][512]
    float2* buf2 = (float2*)(dsm + SM_BUF);        // 16 warps x 512 float2
    float (*tile)[513] = (float (*)[513])buf2;     // epilogue alias
    float*  hbuf = (float*)buf2;                   // MLP hidden alias (prologue)

    // ==== fused MLP: params = silu(t*w1+b1) @ w2 + b2 ====
    {
        float tv = t[b];
        float x = fmaf(tv, w1[tid], b1[tid]);
        if (tid < PPAR) pp[tid] = 0.f;
        hbuf[tid] = x / (1.f + expf(-x));
    }
    __syncthreads();
    {
        float acc0 = 0.f, acc1 = 0.f, acc2 = 0.f;
        const float* w2base = w2 + (wid * 32) * PPAR;
#pragma unroll 8
        for (int k = 0; k < 32; k++) {
            float hv = hbuf[wid * 32 + k];
            const float* wrow = w2base + k * PPAR;
            acc0 = fmaf(hv, wrow[lane], acc0);
            acc1 = fmaf(hv, wrow[lane + 32], acc1);
            if (lane < 8) acc2 = fmaf(hv, wrow[lane + 64], acc2);
        }
        atomicAdd(&pp[lane], acc0);
        atomicAdd(&pp[lane + 32], acc1);
        if (lane < 8) atomicAdd(&pp[lane + 64], acc2);
    }
    __syncthreads();
    if (tid < PPAR) {
        float v = pp[tid] + b2[tid];
        pp[tid] = v;
        if (grp == 0) g_params[b * PPAR + tid] = v;
    }
    __syncthreads();
    // ==== gate trig ====
    if (tid < NGATES) {
        float* dst = &gf[tid * 4];
        dst[0] = cosf(0.5f * pp[2 * tid]);
        dst[1] = sinf(0.5f * pp[2 * tid]);
        dst[2] = cosf(0.5f * pp[2 * tid + 1]);
        dst[3] = sinf(0.5f * pp[2 * tid + 1]);
    }
    __syncthreads();
    // ==== phase subtables ====
    if (tid < 128) {           // plo[L][l]: wires 4..8 (n bits 4..0)
        const int L = tid >> 5, l = tid & 31;
        float pr = 1.f, pi_ = 0.f;
#pragma unroll
        for (int w = 4; w < 9; w++) {
            float cp = gf[(L * 9 + w) * 4 + 2];
            float sp = gf[(L * 9 + w) * 4 + 3];
            float sg = ((l >> (8 - w)) & 1) ? sp : -sp;
            float nr = fmaf(pr, cp, -pi_ * sg);
            float ni = fmaf(pr, sg,  pi_ * cp);
            pr = nr; pi_ = ni;
        }
        plo[L * 32 + l] = make_float2(pr, pi_);
    } else if (tid < 192) {    // phi[L][hh]: wires 0..3 (n bits 8..5), C_L folded (L>=1)
        const int L = (tid - 128) >> 4, hh = tid & 15;
        float pr = 1.f, pi_ = 0.f;
#pragma unroll
        for (int w = 0; w < 4; w++) {
            float cp = gf[(L * 9 + w) * 4 + 2];
            float sp = gf[(L * 9 + w) * 4 + 3];
            float sg = ((hh >> (3 - w)) & 1) ? sp : -sp;
            float nr = fmaf(pr, cp, -pi_ * sg);
            float ni = fmaf(pr, sg,  pi_ * cp);
            pr = nr; pi_ = ni;
        }
        if (L >= 1) {
            float C = 1.f;
#pragma unroll
            for (int w = 0; w < 9; w++) C *= gf[(L * 9 + w) * 4];
            pr *= C; pi_ *= C;
        }
        phi[L * 16 + hh] = make_float2(pr, pi_);
    }
    __syncthreads();
    // ==== full tables: ph[L][.] = plo*phi ====
    // L0: layout-A index of p = pinv9(n): ((p&15)<<5)|(p>>4).  L1-3: linear n.
    {
        const int n = tid;
#pragma unroll
        for (int L = 0; L < NLAYERS; L++) {
            float2 lo = plo[L * 32 + (n & 31)];
            float2 hi = phi[L * 16 + (n >> 5)];
            float pr  = fmaf(lo.x, hi.x, -lo.y * hi.y);
            float pi_ = fmaf(lo.x, hi.y,  lo.y * hi.x);
            int idx = n;
            if (L == 0) {
                int p = pinv9(n);
                idx = ((p & 15) << 5) | (p >> 4);
            }
            ph[L * 512 + idx] = make_float2(pr, pi_);
        }
    }
    __syncthreads();

    const int l0 = lane & 1, l1 = (lane >> 1) & 1, l2 = (lane >> 2) & 1;
    const int l3 = (lane >> 3) & 1, l4 = (lane >> 4) & 1;

    float re[16], im[16];

    // ---- layer 0: analytic (validated R4-R8) ----
    {
        float E0a, E0b, E1a, E1b, E2a, E2b, E3a, E3b, E4a, E4b;
        float E5a, E5b, E6a, E6b, E7a, E7b, E8a, E8b;
#define MKE(W, A, Bv) { float c_ = gf[(W)*4], s_ = gf[(W)*4+1]; \
        int cb = (col >> (8-(W))) & 1; A = cb ? -s_ : c_; Bv = cb ? c_ : s_; }
        MKE(0, E0a, E0b) MKE(1, E1a, E1b) MKE(2, E2a, E2b)
        MKE(3, E3a, E3b) MKE(4, E4a, E4b) MKE(5, E5a, E5b)
        MKE(6, E6a, E6b) MKE(7, E7a, E7b) MKE(8, E8a, E8b)
#undef MKE
        float Plane = ((l0 ^ l1) ? E4b : E4a)
                    * ((l1 ^ l2) ? E3b : E3a)
                    * ((l2 ^ l3) ? E2b : E2a);
        float q3_0 = l0 ? E5b : E5a;
        float q3_1 = l0 ? E5a : E5b;
        int x34 = l3 ^ l4;
        float q78_0 = (x34 ? E1b : E1a) * (l4 ? E0b : E0a);
        float q78_1 = (x34 ? E1a : E1b) * (l4 ? E0a : E0b);
#pragma unroll
        for (int r = 0; r < 16; r++) {
            const int r0 = r & 1, r1 = (r >> 1) & 1, r2 = (r >> 2) & 1, r3 = (r >> 3) & 1;
            float amp = Plane
                      * (r3 ? q3_1 : q3_0)
                      * (r0 ? q78_1 : q78_0)
                      * ((r0 ^ r1) ? E8b : E8a)
                      * ((r1 ^ r2) ? E7b : E7a)
                      * ((r2 ^ r3) ? E6b : E6a);
            float2 p0 = ph[(r << 5) | lane];
            re[r] = amp * p0.x;
            im[r] = amp * p0.y;
        }
    }

    // exchange addressing (validated R8)
    float2* wb = buf2 + wid * 512;
    const int awb = (lane << 4) ^ lane;         // A-write: addr = awb ^ r
    const int lb  = lane ^ (lane >> 4);         // B-read:  addr = s*34 ^ lb
    const int paBase = f2s(cperm(lane << 4));   // exact (not lane*24!)

#pragma unroll 1
    for (int L = 1; L < NLAYERS; L++) {
        const float* gL = gf + L * 36;
        // ---- layout A: wires 5..8, fast-Givens ----
#pragma unroll
        for (int w = 5; w < 9; w++) {
            float tg = __fdividef(gL[w * 4 + 1], gL[w * 4]);
            const int bit = 1 << (8 - w);
#pragma unroll
            for (int ra = 0; ra < 16; ra++) {
                if (ra & bit) continue;
                const int rb = ra | bit;
                float xr = re[ra], yr = re[rb];
                re[ra] = fmaf(-tg, yr, xr);
                re[rb] = fmaf( tg, xr, yr);
                float xi = im[ra], yi = im[rb];
                im[ra] = fmaf(-tg, yi, xi);
                im[rb] = fmaf( tg, xi, yi);
            }
        }
        // ---- transpose A->B (float2, swizzle x^(x>>4)) ----
#pragma unroll
        for (int r = 0; r < 16; r++) wb[awb ^ r] = make_float2(re[r], im[r]);
        __syncwarp();
#pragma unroll
        for (int s = 0; s < 16; s++) {
            float2 v = wb[(s * 34) ^ lb];
            re[s] = v.x; im[s] = v.y;
        }
        __syncwarp();
        // ---- layout B: wires 0..3 ----
#pragma unroll
        for (int w = 0; w < 4; w++) {
            float tg = __fdividef(gL[w * 4 + 1], gL[w * 4]);
            const int bit = 1 << (3 - w);
#pragma unroll
            for (int sa = 0; sa < 16; sa++) {
                if (sa & bit) continue;
                const int sb = sa | bit;
                float xr = re[sa], yr = re[sb];
                re[sa] = fmaf(-tg, yr, xr);
                re[sb] = fmaf( tg, xr, yr);
                float xi = im[sa], yi = im[sb];
                im[sa] = fmaf(-tg, yi, xi);
                im[sb] = fmaf( tg, xi, yi);
            }
        }
        // ---- wire 4: lane bit 4 (shfl) ----
        {
            float tg = __fdividef(gL[4 * 4 + 1], gL[4 * 4]);
            float bt = l4 ? tg : -tg;
#pragma unroll
            for (int s = 0; s < 16; s++) {
                float ore = __shfl_xor_sync(0xffffffffu, re[s], 16);
                float oim = __shfl_xor_sync(0xffffffffu, im[s], 16);
                re[s] = fmaf(bt, ore, re[s]);
                im[s] = fmaf(bt, oim, im[s]);
            }
        }
        if (L < 3) {
            // ---- phase (C_L folded), layout B: n = (s<<5)|lane ----
            const float2* phL = ph + L * 512;
#pragma unroll
            for (int s = 0; s < 16; s++) {
                float2 pq = phL[(s << 5) | lane];
                float tr = fmaf(pq.x, re[s], -(pq.y * im[s]));
                float ti = fmaf(pq.y, re[s],  (pq.x * im[s]));
                re[s] = tr; im[s] = ti;
            }
            // ---- transpose B->A with perm folded (float2, swizzle f2s) ----
#pragma unroll
            for (int s = 0; s < 16; s++) {
                int a = ((s << 5) ^ (s & 15) ^ ((s & 8) << 1)) ^ lane;
                wb[a] = make_float2(re[s], im[s]);
            }
            __syncwarp();
#pragma unroll
            for (int r = 0; r < 16; r++) {
                float2 v = wb[paBase ^ f2s(cperm(r))];
                re[r] = v.x; im[r] = v.y;
            }
            __syncwarp();
        } else {
            // ---- L3: phase re-only; layout B kept, perm folds into tile store ----
            const float2* phL = ph + 3 * 512;
#pragma unroll
            for (int s = 0; s < 16; s++) {
                float2 pq = phL[(s << 5) | lane];
                re[s] = fmaf(pq.x, re[s], -(pq.y * im[s]));
            }
        }
    }

    __syncthreads();   // all warps done with wb; alias buf as tile

    // direct tile store with CNOT perm folded: j = pinv9((s<<5)|lane)
    {
        const int pl = pinv9(lane);
#pragma unroll
        for (int s = 0; s < 16; s++)
            tile[wid][pinv9(s << 5) ^ pl] = re[s];
    }
    __syncthreads();

    // coalesced write: out[b][j][grp*16 + c]
    float* obase = out + (size_t)b * DDIM * DDIM + grp * 16;
    const int c  = tid & 15;
    const int j0 = tid >> 4;   // 0..31
#pragma unroll
    for (int k = 0; k < 16; k++) {
        int j = k * 32 + j0;
        obase[(size_t)j * DDIM + c] = tile[c][j];
    }
}

// ---------------------------------------------------------------------------
// K3: rank-2 expm update; Uv and ||v||^2 computed in-warp from the row.
// One warp per row. C[i,j] += (a1*u0 - a2*Uv_i) v_j (j>=1);
// C[i,0] = ct*u0 - a1*Uv_i.
// ---------------------------------------------------------------------------
__global__ void k3_update(float* __restrict__ out) {
    const int gw   = (blockIdx.x * blockDim.x + threadIdx.x) >> 5;
    const int lane = threadIdx.x & 31;
    const int b = gw >> 9;
    const int i = gw & 511;
    if (b >= BATCH) return;

    const float* gp = g_params + b * PPAR;
    float* row = out + ((size_t)b * DDIM + i) * DDIM;

    float r0 = row[lane];
    float r1 = row[lane + 32];
    float r2 = (lane < 8) ? row[lane + 64] : 0.f;
    float v0 = (lane >= 1) ? 0.01f * gp[lane] : 0.f;
    float v1 = 0.01f * gp[lane + 32];
    float v2 = (lane < 8) ? 0.01f * gp[lane + 64] : 0.f;
    float u0 = __shfl_sync(0xffffffffu, r0, 0);

    float uv = fmaf(r0, v0, fmaf(r1, v1, r2 * v2));
    float s2 = fmaf(v0, v0, fmaf(v1, v1, v2 * v2));
#pragma unroll
    for (int d = 16; d >= 1; d >>= 1) {
        uv += __shfl_xor_sync(0xffffffffu, uv, d);
        s2 += __shfl_xor_sync(0xffffffffu, s2, d);
    }

    float th = sqrtf(s2);
    float ct = cosf(th);
    float a1, a2;
    if (th > 1e-6f) { a1 = sinf(th) / th; a2 = (1.f - ct) / s2; }
    else            { a1 = 1.f - s2 * (1.f / 6.f); a2 = 0.5f; }
    float f = fmaf(a1, u0, -a2 * uv);

    row[lane]      = (lane == 0) ? fmaf(u0, ct, -a1 * uv) : fmaf(f, v0, r0);
    row[lane + 32] = fmaf(f, v1, r1);
    if (lane < 8) row[lane + 64] = fmaf(f, v2, r2);
}

// ---------------------------------------------------------------------------
extern "C" void kernel_launch(void* const* d_in, const int* in_sizes, int n_in,
                              void* d_out, int out_size) {
    const float* t  = (const float*)d_in[0];
    const float* w1 = (const float*)d_in[1];
    const float* b1 = (const float*)d_in[2];
    const float* w2 = (const float*)d_in[3];
    const float* b2 = (const float*)d_in[4];
    float* out = (float*)d_out;

    cudaFuncSetAttribute(k2_sim, cudaFuncAttributeMaxDynamicSharedMemorySize,
                         SM_TOTAL);

    k2_sim<<<BATCH * 32, 512, SM_TOTAL>>>(out, t, w1, b1, w2, b2);
    k3_update<<<(BATCH * DDIM) / 8, 256>>>(out);
}